// round 15
// baseline (speedup 1.0000x reference)
#include <cuda_runtime.h>
#include <cstdint>

#define B 8
#define C 64
#define H 128
#define W 128
#define HW (H * W)            // 16384
#define BHW (B * HW)          // 131072
#define NEVAL 17

#define OUT_TFM_OFF 2
#define OUT_IFM_OFF (2 + BHW)

struct LamParams {
    float lam[4][9];
};

// per-(eval, batch*block) partials: 17 x (8*64)
__device__ double g_part[NEVAL][512];
// interleaved (ifm, iw) for the ssim gathers (written by fmap input-half)
__device__ float2 g_packed[BHW];

// ---------------------------------------------------------------------------
// Kernel 1: calc_fmap — warp spans a full image row (best-known config).
//   Input-half blocks additionally write (ifm, iw) packed for ssim.
// ---------------------------------------------------------------------------
__global__ __launch_bounds__(128)
void fmap_kernel(const float* __restrict__ tfeat, const float* __restrict__ ifeat,
                 const float* __restrict__ iw, float* __restrict__ out)
{
    const int z = blockIdx.y;                 // 0..15
    const int b = z & 7;
    const float* xb = ((z < B) ? tfeat : ifeat) + (size_t)b * C * HW;
    float* ob = out + (size_t)z * HW;

    const int warp = threadIdx.x >> 5;        // 0..3
    const int lane = threadIdx.x & 31;
    const int y    = blockIdx.x * 4 + warp;   // output row
    const int x0   = lane * 4;

    const bool r0ok = (y > 0);
    const bool r2ok = (y < H - 1);
    const float* p0 = xb + (size_t)(y - 1) * W + x0;
    const float* p1 = xb + (size_t)y * W + x0;
    const float* p2 = xb + (size_t)(y + 1) * W + x0;

    float A[4][9];
    float P[3][4], Q[3][4];
#pragma unroll
    for (int i = 0; i < 4; i++)
#pragma unroll
        for (int k = 0; k < 9; k++) A[i][k] = 0.f;
#pragma unroll
    for (int r = 0; r < 3; r++)
#pragma unroll
        for (int i = 0; i < 4; i++) { P[r][i] = 0.f; Q[r][i] = 0.f; }

    for (int c = 0; c < C; c++) {
        float4 v[3];
        v[0] = r0ok ? __ldg((const float4*)(p0)) : make_float4(0.f, 0.f, 0.f, 0.f);
        v[1] = __ldg((const float4*)(p1));
        v[2] = r2ok ? __ldg((const float4*)(p2)) : make_float4(0.f, 0.f, 0.f, 0.f);
        p0 += HW; p1 += HW; p2 += HW;

        float e[3][6];
        float rowsum[3][4];
#pragma unroll
        for (int r = 0; r < 3; r++) {
            float L = __shfl_up_sync(0xffffffffu, v[r].w, 1);
            float R = __shfl_down_sync(0xffffffffu, v[r].x, 1);
            if (lane == 0)  L = 0.f;
            if (lane == 31) R = 0.f;
            e[r][0] = L; e[r][1] = v[r].x; e[r][2] = v[r].y;
            e[r][3] = v[r].z; e[r][4] = v[r].w; e[r][5] = R;
            float t01 = e[r][0] + e[r][1];
            float t23 = e[r][2] + e[r][3];
            float t45 = e[r][4] + e[r][5];
            rowsum[r][0] = t01 + e[r][2];
            rowsum[r][1] = e[r][1] + t23;
            rowsum[r][2] = t23 + e[r][4];
            rowsum[r][3] = e[r][3] + t45;
            P[r][0] += v[r].x; P[r][1] += v[r].y; P[r][2] += v[r].z; P[r][3] += v[r].w;
            Q[r][0] = fmaf(v[r].x, v[r].x, Q[r][0]);
            Q[r][1] = fmaf(v[r].y, v[r].y, Q[r][1]);
            Q[r][2] = fmaf(v[r].z, v[r].z, Q[r][2]);
            Q[r][3] = fmaf(v[r].w, v[r].w, Q[r][3]);
        }

        float s[4];
#pragma unroll
        for (int i = 0; i < 4; i++)
            s[i] = rowsum[0][i] + rowsum[1][i] + rowsum[2][i];

#pragma unroll
        for (int i = 0; i < 4; i++)
#pragma unroll
            for (int r = 0; r < 3; r++)
#pragma unroll
                for (int d = 0; d < 3; d++)
                    A[i][r * 3 + d] = fmaf(e[r][i + d], s[i], A[i][r * 3 + d]);
    }

    // one-time halo exchange of P/Q columns x0-1 and x0+4
    float PL[3], PR[3], QL[3], QR[3];
#pragma unroll
    for (int r = 0; r < 3; r++) {
        PL[r] = __shfl_up_sync(0xffffffffu, P[r][3], 1);
        QL[r] = __shfl_up_sync(0xffffffffu, Q[r][3], 1);
        PR[r] = __shfl_down_sync(0xffffffffu, P[r][0], 1);
        QR[r] = __shfl_down_sync(0xffffffffu, Q[r][0], 1);
        if (lane == 0)  { PL[r] = 0.f; QL[r] = 0.f; }
        if (lane == 31) { PR[r] = 0.f; QR[r] = 0.f; }
    }

    float res[4];
#pragma unroll
    for (int i = 0; i < 4; i++) {
        float S1[9], T2 = 0.f;
#pragma unroll
        for (int r = 0; r < 3; r++)
#pragma unroll
            for (int d = 0; d < 3; d++) {
                int col = i - 1 + d;
                float pv = (col < 0) ? PL[r] : (col > 3) ? PR[r] : P[r][col];
                float qv = (col < 0) ? QL[r] : (col > 3) ? QR[r] : Q[r][col];
                S1[r * 3 + d] = pv;
                T2 += qv;
            }
        float mu[9], M = 0.f, musq = 0.f;
#pragma unroll
        for (int k = 0; k < 9; k++) {
            mu[k] = S1[k] * (1.f / C);
            M += mu[k];
            musq = fmaf(mu[k], mu[k], musq);
        }
        float trace = T2 - (float)C * musq;

        float rmax = -3.4e38f, rmin = 3.4e38f;
#pragma unroll
        for (int k = 0; k < 9; k++) {
            float rsv = A[i][k] - (float)C * mu[k] * M;
            rmax = fmaxf(rmax, rsv);
            rmin = fminf(rmin, rsv);
        }
        res[i] = (rmax + rmin) * 0.5f / trace;
    }
    // scalar stores: output base is only 8B-aligned (d_out + 2 floats)
    float* op = ob + (size_t)y * W + x0;
    op[0] = res[0];
    op[1] = res[1];
    op[2] = res[2];
    op[3] = res[3];

    // input half also writes the packed (ifm, iw) array for ssim
    if (z >= B) {
        const size_t base = (size_t)b * HW + (size_t)y * W + x0;
        const float* iwp = iw + base;
        float2* pk = g_packed + base;
#pragma unroll
        for (int i = 0; i < 4; i++)
            pk[i] = make_float2(res[i], __ldg(&iwp[i]));
    }
}

// ---------------------------------------------------------------------------
// per-eval bilinear + accumulate body
// ---------------------------------------------------------------------------
__device__ __forceinline__ float ssim_eval(float X, float Y, float Z,
                                           const float2* __restrict__ pk,
                                           float t0, float tw0)
{
    float invZ = __fdividef(1.f, Z);
    float px = X * invZ;
    float py = Y * invZ;

    float x0f = floorf(px), y0f = floorf(py);
    float x1f = x0f + 1.f,  y1f = y0f + 1.f;

    float vx0 = (x0f >= 0.f && x0f <= (float)(W - 1)) ? 1.f : 0.f;
    float vx1 = (x1f >= 0.f && x1f <= (float)(W - 1)) ? 1.f : 0.f;
    float vy0 = (y0f >= 0.f && y0f <= (float)(H - 1)) ? 1.f : 0.f;
    float vy1 = (y1f >= 0.f && y1f <= (float)(H - 1)) ? 1.f : 0.f;
    int xc0 = (int)fminf(fmaxf(x0f, 0.f), (float)(W - 1));
    int xc1 = (int)fminf(fmaxf(x1f, 0.f), (float)(W - 1));
    int row0 = ((int)fminf(fmaxf(y0f, 0.f), (float)(H - 1))) * W;
    int row1 = ((int)fminf(fmaxf(y1f, 0.f), (float)(H - 1))) * W;

    float ax0 = x1f - px, ax1 = px - x0f;
    float ay0 = y1f - py, ay1 = py - y0f;

    float2 gA = __ldg(&pk[row0 + xc0]);
    float2 gB = __ldg(&pk[row1 + xc0]);
    float2 gC = __ldg(&pk[row0 + xc1]);
    float2 gD = __ldg(&pk[row1 + xc1]);

    float wA = ax0 * ay0 * (vx0 * vy0);
    float wB = ax0 * ay1 * (vx0 * vy1);
    float wC = ax1 * ay0 * (vx1 * vy0);
    float wD = ax1 * ay1 * (vx1 * vy1);

    float wfm = wA * gA.x;
    float ww  = wA * gA.y;
    wfm = fmaf(wB, gB.x, wfm);
    ww  = fmaf(wB, gB.y, ww);
    wfm = fmaf(wC, gC.x, wfm);
    ww  = fmaf(wC, gC.y, ww);
    wfm = fmaf(wD, gD.x, wfm);
    ww  = fmaf(wD, gD.y, ww);

    float d = t0 - wfm;
    return (tw0 * ww) * (d * d);
}

// ---------------------------------------------------------------------------
// Kernel 2: ssim v5 — eval-parallel: grid.z = 4 noise-dir groups.
//   Group 0: base eval + n=0's 4 evals (5). Groups 1-3: their n's 4 evals.
//   Grid (64, 8, 4) = 2048 blocks, block 256.
// ---------------------------------------------------------------------------
__global__ __launch_bounds__(256)
void ssim_kernel(const float* __restrict__ tfm,
                 const float* __restrict__ tw,
                 const float* __restrict__ Hgt, LamParams P)
{
    const int g   = blockIdx.z;               // 0..3 (noise dir)
    const int b   = blockIdx.y;
    const int idx = blockIdx.x * 256 + threadIdx.x;

    float Hg[9];
#pragma unroll
    for (int i = 0; i < 9; i++)
        Hg[i] = __ldg(&Hgt[b * 9 + i]);

    const int y = idx >> 7;
    const int x = idx & 127;
    const float fx = (float)x, fy = (float)y;

    const float2* pk = g_packed + (size_t)b * HW;
    const float t0   = __ldg(&tfm[(size_t)b * HW + idx]);
    const float tw0  = __ldg(&tw[(size_t)b * HW + idx]);

    // base projection
    const float bx = fmaf(Hg[0], fx, fmaf(Hg[1], fy, Hg[2]));
    const float by = fmaf(Hg[3], fx, fmaf(Hg[4], fy, Hg[5]));
    const float bz = fmaf(Hg[6], fx, fmaf(Hg[7], fy, Hg[8]));

    // perturbation projection for this group's noise dir
    const float pxn = fmaf(Hg[0] * P.lam[g][0], fx,
                      fmaf(Hg[1] * P.lam[g][1], fy, Hg[2] * P.lam[g][2]));
    const float pyn = fmaf(Hg[3] * P.lam[g][3], fx,
                      fmaf(Hg[4] * P.lam[g][4], fy, Hg[5] * P.lam[g][5]));
    const float pzn = fmaf(Hg[6] * P.lam[g][6], fx,
                      fmaf(Hg[7] * P.lam[g][7], fy, Hg[8] * P.lam[g][8]));

    float acc[5];
#pragma unroll
    for (int j = 0; j < 4; j++) {
        const float cf = (j == 0) ? 1.f : (j == 1) ? 2.f : (j == 2) ? -1.f : -2.f;
        float X = fmaf(cf, pxn, bx);
        float Y = fmaf(cf, pyn, by);
        float Z = fmaf(cf, pzn, bz);
        acc[j] = ssim_eval(X, Y, Z, pk, t0, tw0);
    }
    const bool has5 = (g == 0);
    acc[4] = has5 ? ssim_eval(bx, by, bz, pk, t0, tw0) : 0.f;

    // reduce: local eval le -> global eval: le<4 -> 4g+1+le ; le==4 -> 0
    const int lane = threadIdx.x & 31;
    const int warp = threadIdx.x >> 5;
    __shared__ float wsum[8][5];
#pragma unroll
    for (int le = 0; le < 5; le++) {
        float v = acc[le];
#pragma unroll
        for (int o = 16; o > 0; o >>= 1)
            v += __shfl_down_sync(0xffffffffu, v, o);
        if (lane == 0) wsum[warp][le] = v;
    }
    __syncthreads();
    if (threadIdx.x < 5 && (threadIdx.x < 4 || has5)) {
        const int le = threadIdx.x;
        float s = 0.f;
#pragma unroll
        for (int w2 = 0; w2 < 8; w2++) s += wsum[w2][le];
        const int e = (le == 4) ? 0 : (4 * g + 1 + le);
        g_part[e][b * 64 + blockIdx.x] = (double)s;
    }
}

// ---------------------------------------------------------------------------
// Kernel 3: final reduce + combine (single block, 512 threads)
// ---------------------------------------------------------------------------
__global__ __launch_bounds__(512)
void final_kernel(float* __restrict__ out, LamParams P)
{
    __shared__ double sums[NEVAL];
    __shared__ double wred[16];
    const int t = threadIdx.x;
    const int lane = t & 31, warp = t >> 5;

    for (int e = 0; e < NEVAL; e++) {
        double s = g_part[e][t];
#pragma unroll
        for (int o = 16; o > 0; o >>= 1)
            s += __shfl_down_sync(0xffffffffu, s, o);
        if (lane == 0) wred[warp] = s;
        __syncthreads();
        if (warp == 0) {
            double v = (lane < 16) ? wred[lane] : 0.0;
#pragma unroll
            for (int o = 8; o > 0; o >>= 1)
                v += __shfl_down_sync(0xffffffffu, v, o);
            if (lane == 0) sums[e] = v;
        }
        __syncthreads();
    }

    if (t == 0) {
        const double inv = 1.0 / (double)BHW;
        double mid = sums[0] * inv;
        double loss = 0.0;
#pragma unroll
        for (int n = 0; n < 4; n++) {
            double sL  = sums[1 + 4 * n] * inv;
            double sLL = sums[2 + 4 * n] * inv;
            double sR  = sums[3 + 4 * n] * inv;
            double sRR = sums[4 + 4 * n] * inv;
            float s2f = 0.f;
#pragma unroll
            for (int i = 0; i < 9; i++) s2f = fmaf(P.lam[n][i], P.lam[n][i], s2f);
            double s2 = (double)s2f;
            double d2 = 3.0 * s2;
            loss -= fmin(sL - mid - s2, 0.0);
            loss -= fmin(sL - sLL + d2, 0.0);
            loss -= fmin(sR - mid - s2, 0.0);
            loss -= fmin(sR - sRR + d2, 0.0);
        }
        out[0] = (float)loss;
        out[1] = (float)mid;
    }
}

// ---------------------------------------------------------------------------
// Host: JAX Threefry (partitionable) for gen_lambda
// ---------------------------------------------------------------------------
static inline void threefry2x32(uint32_t k0, uint32_t k1,
                                uint32_t x0, uint32_t x1,
                                uint32_t* o0, uint32_t* o1)
{
    const uint32_t ks[3] = {k0, k1, k0 ^ k1 ^ 0x1BD11BDAu};
    uint32_t v0 = x0 + ks[0];
    uint32_t v1 = x1 + ks[1];
    static const int rot[2][4] = {{13, 15, 26, 6}, {17, 29, 16, 24}};
    for (int g = 0; g < 5; g++) {
        const int* r = rot[g & 1];
        for (int i = 0; i < 4; i++) {
            v0 += v1;
            v1 = (v1 << r[i]) | (v1 >> (32 - r[i]));
            v1 ^= v0;
        }
        v0 += ks[(g + 1) % 3];
        v1 += ks[(g + 2) % 3] + (uint32_t)(g + 1);
    }
    *o0 = v0;
    *o1 = v1;
}

static void compute_lambdas(LamParams* P)
{
    for (int n = 0; n < 4; n++) {
        uint32_t k0, k1;
        threefry2x32(0u, 42u, 0u, (uint32_t)n, &k0, &k1);
        for (int i = 0; i < 9; i++) {
            uint32_t o0, o1;
            threefry2x32(k0, k1, 0u, (uint32_t)i, &o0, &o1);
            uint32_t bits = o0 ^ o1;
            uint32_t fb = (bits >> 9) | 0x3f800000u;
            float u;
            __builtin_memcpy(&u, &fb, 4);
            u -= 1.0f;
            float lam = (u - 0.5f) / 6.0f;
            if (lam > 0.f && lam < 0.02f)  lam = 0.02f;
            if (lam < 0.f && lam > -0.02f) lam = -0.02f;
            P->lam[n][i] = lam;
        }
        P->lam[n][8] = 0.0f;
    }
}

// ---------------------------------------------------------------------------
// Entry point
// ---------------------------------------------------------------------------
extern "C" void kernel_launch(void* const* d_in, const int* in_sizes, int n_in,
                              void* d_out, int out_size)
{
    (void)in_sizes; (void)n_in; (void)out_size;
    const float* tfeat = (const float*)d_in[0];
    const float* ifeat = (const float*)d_in[1];
    const float* tw    = (const float*)d_in[2];
    const float* iw    = (const float*)d_in[3];
    const float* Hgt   = (const float*)d_in[4];
    float* out = (float*)d_out;

    LamParams P;
    compute_lambdas(&P);

    float* tfm = out + OUT_TFM_OFF;

    dim3 fgrd(H / 4, 2 * B);              // (32, 16) = 512 blocks of 128
    fmap_kernel<<<fgrd, 128>>>(tfeat, ifeat, iw, tfm);

    dim3 sgrd(HW / 256, B, 4);            // (64, 8, 4) = 2048 blocks of 256
    ssim_kernel<<<sgrd, 256>>>(tfm, tw, Hgt, P);

    final_kernel<<<1, 512>>>(out, P);
}